// round 6
// baseline (speedup 1.0000x reference)
#include <cuda_runtime.h>
#include <math.h>

#define T_STEPS 300
#define DIN 39
#define H1D 35
#define H1P 36          // padded units (unit 35 = dummy zeros)
#define H2D 30
#define G1 140
#define G1P 144         // padded gate count (36 units * 4)
#define G2 120
#define K1 74
#define K2 65
#define BT 64
#define BTP 68
#define NT 576
#define HALF_T 288      // threads per independent half (9 warps)
#define BATCH 4096
#define NBLK (BATCH/BT)

typedef unsigned long long ull;

// ---- shared memory layout (float offsets) ----
#define OFF_W1D 0                          // 74*288 (duplicated, unit-major, padded)
#define OFF_W2D (OFF_W1D + K1*2*G1P)       // size 65*240
#define OFF_B1  (OFF_W2D + K2*2*G2)
#define OFF_B2  (OFF_B1 + G1P)
#define OFF_X   (OFF_B2 + G2)              // 2*39*68
#define OFF_H1  (OFF_X + 2*DIN*BTP)        // 2*36*68
#define OFF_H2  (OFF_H1 + 2*H1P*BTP)       // 2*30*68
#define SM_FLOATS (OFF_H2 + 2*H2D*BTP)     // 51456 floats = 205824 B

#define X_BUF  (DIN*BTP)
#define H1_BUF (H1P*BTP)
#define H2_BUF (H2D*BTP)

// scratch for LSTM hidden states: [T][60][B], fw units in [0,30), bw in [30,60)
__device__ float g_hbuf[(size_t)BATCH * T_STEPS * 60];

__device__ __forceinline__ ull fma2(ull a, ull b, ull c) {
    ull d;
    asm("fma.rn.f32x2 %0, %1, %2, %3;" : "=l"(d) : "l"(a), "l"(b), "l"(c));
    return d;
}
__device__ __forceinline__ ull pack2(float lo, float hi) {
    ull d;
    asm("mov.b64 %0, {%1, %2};" : "=l"(d) : "f"(lo), "f"(hi));
    return d;
}
__device__ __forceinline__ void unpack2(ull v, float& lo, float& hi) {
    asm("mov.b64 {%0, %1}, %2;" : "=f"(lo), "=f"(hi) : "l"(v));
}

__device__ __forceinline__ float sigf(float x) {
    return __fdividef(1.0f, 1.0f + __expf(-x));
}
__device__ __forceinline__ float tanhfast(float x) {
    return 2.0f * sigf(2.0f * x) - 1.0f;
}

// cell update on a packed pair of batch lanes; gate order i, j, f, o
__device__ __forceinline__ void cell2(ull zi, ull zj, ull zf, ull zo,
                                      ull& c, float& h0, float& h1)
{
    float i0,i1,j0,j1,f0,f1,o0,o1,c0,c1;
    unpack2(zi,i0,i1); unpack2(zj,j0,j1);
    unpack2(zf,f0,f1); unpack2(zo,o0,o1);
    unpack2(c,c0,c1);
    c0 = sigf(f0 + 1.0f) * c0 + sigf(i0) * tanhfast(j0);
    c1 = sigf(f1 + 1.0f) * c1 + sigf(i1) * tanhfast(j1);
    h0 = sigf(o0) * tanhfast(c0);
    h1 = sigf(o1) * tanhfast(c1);
    c = pack2(c0, c1);
}

// 4-gate x 2-packed-batch tile (4 batch lanes per thread).
// wd: duplicated weights (ull view, WS ull per k row); a: activation row.
template<int KN, int WS>
__device__ __forceinline__ void gemm2(ull (&acc)[4][2],
                                      const ull* __restrict__ wd,
                                      const float* __restrict__ a)
{
    #pragma unroll 5
    for (int k = 0; k < KN; ++k) {
        ulonglong2 w01 = *(const ulonglong2*)(wd);
        ulonglong2 w23 = *(const ulonglong2*)(wd + 2);
        ulonglong2 av  = *(const ulonglong2*)(a);
        wd += WS; a += BTP;
        acc[0][0] = fma2(w01.x, av.x, acc[0][0]);
        acc[0][1] = fma2(w01.x, av.y, acc[0][1]);
        acc[1][0] = fma2(w01.y, av.x, acc[1][0]);
        acc[1][1] = fma2(w01.y, av.y, acc[1][1]);
        acc[2][0] = fma2(w23.x, av.x, acc[2][0]);
        acc[2][1] = fma2(w23.x, av.y, acc[2][1]);
        acc[3][0] = fma2(w23.y, av.x, acc[3][0]);
        acc[3][1] = fma2(w23.y, av.y, acc[3][1]);
    }
}

extern __shared__ float smem[];

__global__ void __launch_bounds__(NT)
lstm_kernel(const float* __restrict__ x,
            const float* __restrict__ fw_W1, const float* __restrict__ fw_b1,
            const float* __restrict__ fw_W2, const float* __restrict__ fw_b2,
            const float* __restrict__ bw_W1, const float* __restrict__ bw_b1,
            const float* __restrict__ bw_W2, const float* __restrict__ bw_b2)
{
    const int dir = blockIdx.y;
    const int b0  = blockIdx.x * BT;
    const int tid = threadIdx.x;

    float* W1d = smem + OFF_W1D;
    float* W2d = smem + OFF_W2D;
    float* b1p = smem + OFF_B1;
    float* b2p = smem + OFF_B2;
    float* xT  = smem + OFF_X;
    float* h1T = smem + OFF_H1;
    float* h2T = smem + OFF_H2;

    const float* W1g = dir ? bw_W1 : fw_W1;
    const float* b1g = dir ? bw_b1 : fw_b1;
    const float* W2g = dir ? bw_W2 : fw_W2;
    const float* b2g = dir ? bw_b2 : fw_b2;

    // permute (unit-major gate order i,j,f,o) + duplicate weights for f32x2.
    // layer 1 padded to 36 units; unit 35 is all-zero.
    for (int i = tid; i < K1*G1P; i += NT) {
        int k = i / G1P, col = i - k * G1P;
        int u = col >> 2, g = col & 3;
        float w = (u < H1D) ? W1g[k*G1 + g*H1D + u] : 0.f;
        W1d[k*2*G1P + 2*col]     = w;
        W1d[k*2*G1P + 2*col + 1] = w;
    }
    for (int i = tid; i < K2*G2; i += NT) {
        int k = i / G2, col = i - k * G2;
        int u = col >> 2, g = col & 3;
        float w = W2g[k*G2 + g*H2D + u];
        W2d[k*2*G2 + 2*col]     = w;
        W2d[k*2*G2 + 2*col + 1] = w;
    }
    for (int i = tid; i < G1P; i += NT) {
        int u = i >> 2, g = i & 3;
        b1p[i] = (u < H1D) ? b1g[g*H1D + u] : 0.f;
    }
    for (int i = tid; i < G2; i += NT) { int u = i >> 2, g = i & 3; b2p[i] = b2g[g*H2D + u]; }
    for (int i = tid; i < H1_BUF; i += NT) { h1T[i] = 0.f; h1T[H1_BUF + i] = 0.f; }
    for (int i = tid; i < H2_BUF; i += NT) { h2T[i] = 0.f; h2T[H2_BUF + i] = 0.f; }

    // stage x for t=0 into buffer 0
    {
        const int tx0 = dir ? (T_STEPS - 1) : 0;
        for (int i = tid; i < DIN*BT; i += NT) {
            int b = i / DIN, d = i - b * DIN;
            xT[d * BTP + b] = x[((size_t)(b0 + b) * T_STEPS + tx0) * DIN + d];
        }
    }
    __syncthreads();

    // ---- independent-half decomposition: halves own disjoint batch lanes ----
    const int half  = (tid >= HALF_T) ? 1 : 0;
    const int local = tid - half * HALF_T;      // 0..287
    const int unit  = local >> 3;               // 0..35 (35 = dummy in layer 1)
    const int bcol  = half * 32 + (local & 7) * 4;   // 4 batch lanes per thread
    const int barid = half + 1;

    ull c1r[2] = {0,0};
    ull c2r[2] = {0,0};

    int cur = 0;

    for (int t = 0; t < T_STEPS; ++t) {
        const int nxt = cur ^ 1;
        const float* xc  = xT  + cur * X_BUF;
        const float* h1c = h1T + cur * H1_BUF;
        float*       h1n = h1T + nxt * H1_BUF;
        const float* h2c = h2T + cur * H2_BUF;
        float*       h2n = h2T + nxt * H2_BUF;

        // ====== Phase A: layer 1 — 36 units x 8 lane-chunks per half ======
        {
            ull acc[4][2];
            #pragma unroll
            for (int g = 0; g < 4; ++g) {
                float bb = b1p[unit*4 + g];
                ull bp = pack2(bb, bb);
                acc[g][0] = bp; acc[g][1] = bp;
            }
            const ull* wd = (const ull*)W1d + unit*4;
            gemm2<DIN, G1P>(acc, wd,             xc  + bcol);
            gemm2<H1D, G1P>(acc, wd + DIN*G1P,   h1c + bcol);

            float h[4];
            cell2(acc[0][0], acc[1][0], acc[2][0], acc[3][0], c1r[0], h[0], h[1]);
            cell2(acc[0][1], acc[1][1], acc[2][1], acc[3][1], c1r[1], h[2], h[3]);
            *(float4*)(h1n + unit*BTP + bcol) = make_float4(h[0], h[1], h[2], h[3]);
        }
        asm volatile("bar.sync %0, %1;" :: "r"(barid), "n"(HALF_T) : "memory");

        // ====== Phase B: layer 2 (units 0..29) + x staging (units 30..35) ======
        if (unit < 30) {
            ull acc[4][2];
            #pragma unroll
            for (int g = 0; g < 4; ++g) {
                float bb = b2p[unit*4 + g];
                ull bp = pack2(bb, bb);
                acc[g][0] = bp; acc[g][1] = bp;
            }
            const ull* wd = (const ull*)W2d + unit*4;
            gemm2<H1D, G2>(acc, wd,            h1n + bcol);
            gemm2<H2D, G2>(acc, wd + H1D*G2,   h2c + bcol);

            float h[4];
            cell2(acc[0][0], acc[1][0], acc[2][0], acc[3][0], c2r[0], h[0], h[1]);
            cell2(acc[0][1], acc[1][1], acc[2][1], acc[3][1], c2r[1], h[2], h[3]);
            *(float4*)(h2n + unit*BTP + bcol) = make_float4(h[0], h[1], h[2], h[3]);

            const int tx = dir ? (T_STEPS - 1 - t) : t;
            // coalesced: [t][feat][batch]
            *(float4*)(&g_hbuf[((size_t)(tx*60 + dir*H2D + unit))*BATCH + b0 + bcol]) =
                make_float4(h[0], h[1], h[2], h[3]);
        } else if (t + 1 < T_STEPS) {
            // 48 threads per half stage x_{t+1} for this half's 32 lanes
            const int txn = dir ? (T_STEPS - 2 - t) : (t + 1);
            float* xn = xT + nxt * X_BUF;
            const int lb0 = half * 32;     // this half's lane base
            #pragma unroll 4
            for (int i = local - 240; i < DIN*32; i += 48) {
                int b = i / DIN, d = i - b * DIN;
                xn[d * BTP + lb0 + b] =
                    x[((size_t)(b0 + lb0 + b) * T_STEPS + txn) * DIN + d];
            }
        }
        asm volatile("bar.sync %0, %1;" :: "r"(barid), "n"(HALF_T) : "memory");
        cur = nxt;
    }
}

// =============================== FC head ===================================
#define FCT 128
#define FOFF_W1 0                       // 60*52 (padded cols 50,51 = 0)
#define FOFF_W2 (FOFF_W1 + 60*52)       // 3120, size 2000
#define FOFF_W3 (FOFF_W2 + 50*40)       // 5120, size 80
#define FOFF_B1 (FOFF_W3 + 80)          // 5200, size 52
#define FOFF_B2 (FOFF_B1 + 52)          // 5252, size 40
#define FOFF_B3 (FOFF_B2 + 40)          // 5292, size 4
#define FOFF_IN (FOFF_B3 + 4)           // 5296, size FCT*61
#define FSM_FLOATS (FOFF_IN + FCT*61)

__global__ void __launch_bounds__(FCT)
fc_kernel(const float* __restrict__ Wf1, const float* __restrict__ bf1,
          const float* __restrict__ Wf2, const float* __restrict__ bf2,
          const float* __restrict__ Wf3, const float* __restrict__ bf3,
          float* __restrict__ out)
{
    extern __shared__ float fsm[];
    float* W1s = fsm + FOFF_W1;
    float* W2s = fsm + FOFF_W2;
    float* W3s = fsm + FOFF_W3;
    float* B1s = fsm + FOFF_B1;
    float* B2s = fsm + FOFF_B2;
    float* B3s = fsm + FOFF_B3;
    float* INs = fsm + FOFF_IN;

    const int tid = threadIdx.x;

    for (int i = tid; i < 60*52; i += FCT) {
        int k = i / 52, j = i - k * 52;
        W1s[i] = (j < 50) ? Wf1[k*50 + j] : 0.f;
    }
    for (int i = tid; i < 50*40; i += FCT) W2s[i] = Wf2[i];
    for (int i = tid; i < 80;    i += FCT) W3s[i] = Wf3[i];
    for (int i = tid; i < 52;    i += FCT) B1s[i] = (i < 50) ? bf1[i] : 0.f;
    for (int i = tid; i < 40;    i += FCT) B2s[i] = bf2[i];
    for (int i = tid; i < 2;     i += FCT) B3s[i] = bf3[i];

    // block = (batch tile, timestep): hbuf reads coalesced in [t][feat][B] layout
    const int bi = blockIdx.x & 31;          // 32 tiles of 128 batch
    const int t  = blockIdx.x >> 5;          // 0..299
    const int b0 = bi * FCT;

    for (int i = tid; i < FCT*60; i += FCT) {
        int f = i >> 7, b = i & 127;
        INs[b*61 + f] = g_hbuf[((size_t)(t*60 + f))*BATCH + b0 + b];
    }
    __syncthreads();

    // fc1: 60 -> 50 (padded 52), packed f32x2 accumulators
    ull acc1[26];
    #pragma unroll
    for (int j = 0; j < 26; ++j) acc1[j] = pack2(B1s[2*j], B1s[2*j+1]);
    #pragma unroll 4
    for (int k = 0; k < 60; ++k) {
        float v = INs[tid*61 + k];
        ull vv = pack2(v, v);
        #pragma unroll
        for (int j = 0; j < 13; ++j) {
            ulonglong2 w = *(const ulonglong2*)(W1s + k*52 + j*4);
            acc1[2*j]   = fma2(vv, w.x, acc1[2*j]);
            acc1[2*j+1] = fma2(vv, w.y, acc1[2*j+1]);
        }
    }
    float a1[52];
    #pragma unroll
    for (int j = 0; j < 26; ++j) {
        float lo, hi; unpack2(acc1[j], lo, hi);
        a1[2*j]   = fmaxf(lo, 0.f);
        a1[2*j+1] = fmaxf(hi, 0.f);
    }

    // fc2: 50 -> 40
    ull acc2[20];
    #pragma unroll
    for (int j = 0; j < 20; ++j) acc2[j] = pack2(B2s[2*j], B2s[2*j+1]);
    #pragma unroll 5
    for (int k = 0; k < 50; ++k) {
        ull vv = pack2(a1[k], a1[k]);
        #pragma unroll
        for (int j = 0; j < 10; ++j) {
            ulonglong2 w = *(const ulonglong2*)(W2s + k*40 + j*4);
            acc2[2*j]   = fma2(vv, w.x, acc2[2*j]);
            acc2[2*j+1] = fma2(vv, w.y, acc2[2*j+1]);
        }
    }
    float a2[40];
    #pragma unroll
    for (int j = 0; j < 20; ++j) {
        float lo, hi; unpack2(acc2[j], lo, hi);
        a2[2*j]   = fmaxf(lo, 0.f);
        a2[2*j+1] = fmaxf(hi, 0.f);
    }

    // out: 40 -> 2
    float o0 = B3s[0], o1 = B3s[1];
    #pragma unroll
    for (int k = 0; k < 40; ++k) {
        o0 = fmaf(a2[k], W3s[2*k + 0], o0);
        o1 = fmaf(a2[k], W3s[2*k + 1], o1);
    }
    // out layout [B][T][2]
    float2 ov = make_float2(o0, o1);
    *(float2*)(&out[((size_t)(b0 + tid) * T_STEPS + t) * 2]) = ov;
}

// ============================================================================
extern "C" void kernel_launch(void* const* d_in, const int* in_sizes, int n_in,
                              void* d_out, int out_size)
{
    const float* x     = (const float*)d_in[0];
    const float* fw_W1 = (const float*)d_in[1];
    const float* fw_b1 = (const float*)d_in[2];
    const float* fw_W2 = (const float*)d_in[3];
    const float* fw_b2 = (const float*)d_in[4];
    const float* bw_W1 = (const float*)d_in[5];
    const float* bw_b1 = (const float*)d_in[6];
    const float* bw_W2 = (const float*)d_in[7];
    const float* bw_b2 = (const float*)d_in[8];
    const float* Wf1   = (const float*)d_in[9];
    const float* bf1   = (const float*)d_in[10];
    const float* Wf2   = (const float*)d_in[11];
    const float* bf2   = (const float*)d_in[12];
    const float* Wf3   = (const float*)d_in[13];
    const float* bf3   = (const float*)d_in[14];

    cudaFuncSetAttribute(lstm_kernel, cudaFuncAttributeMaxDynamicSharedMemorySize,
                         SM_FLOATS * (int)sizeof(float));
    cudaFuncSetAttribute(fc_kernel, cudaFuncAttributeMaxDynamicSharedMemorySize,
                         FSM_FLOATS * (int)sizeof(float));

    lstm_kernel<<<dim3(NBLK, 2), NT, SM_FLOATS * sizeof(float)>>>(
        x, fw_W1, fw_b1, fw_W2, fw_b2, bw_W1, bw_b1, bw_W2, bw_b2);

    fc_kernel<<<32 * T_STEPS, FCT, FSM_FLOATS * sizeof(float)>>>(
        Wf1, bf1, Wf2, bf2, Wf3, bf3, (float*)d_out);
}

// round 7
// speedup vs baseline: 1.2110x; 1.2110x over previous
#include <cuda_runtime.h>
#include <math.h>

#define T_STEPS 300
#define DIN 39
#define H1D 35
#define H1P 36          // padded units (unit 35 = dummy zeros)
#define H2D 30
#define G1 140
#define G1P 144         // padded gate count (36 units * 4)
#define G2 120
#define K1 74
#define K2 65
#define BT 64
#define BTP 68
#define NT 576
#define BATCH 4096
#define NBLK (BATCH/BT)

typedef unsigned long long ull;

// ---- shared memory layout (float offsets) ----
#define OFF_W1D 0                          // 74*288 (duplicated, unit-major, padded)
#define OFF_W2D (OFF_W1D + K1*2*G1P)       // size 65*240
#define OFF_B1  (OFF_W2D + K2*2*G2)
#define OFF_B2  (OFF_B1 + G1P)
#define OFF_X   (OFF_B2 + G2)              // 2*39*68
#define OFF_H1  (OFF_X + 2*DIN*BTP)        // 2*36*68
#define OFF_H2  (OFF_H1 + 2*H1P*BTP)       // 2*30*68
#define SM_FLOATS (OFF_H2 + 2*H2D*BTP)     // 51456 floats = 205824 B

#define X_BUF  (DIN*BTP)
#define H1_BUF (H1P*BTP)
#define H2_BUF (H2D*BTP)

// scratch: LSTM hidden states [T][60][B]  (fw units [0,30), bw [30,60))
__device__ float g_hbuf[(size_t)BATCH * T_STEPS * 60];
// scratch: transposed input [T][D][B]
__device__ float g_xT[(size_t)T_STEPS * DIN * BATCH];

__device__ __forceinline__ ull fma2(ull a, ull b, ull c) {
    ull d;
    asm("fma.rn.f32x2 %0, %1, %2, %3;" : "=l"(d) : "l"(a), "l"(b), "l"(c));
    return d;
}
__device__ __forceinline__ ull pack2(float lo, float hi) {
    ull d;
    asm("mov.b64 %0, {%1, %2};" : "=l"(d) : "f"(lo), "f"(hi));
    return d;
}
__device__ __forceinline__ void unpack2(ull v, float& lo, float& hi) {
    asm("mov.b64 {%0, %1}, %2;" : "=f"(lo), "=f"(hi) : "l"(v));
}

__device__ __forceinline__ float sigf(float x) {
    return __fdividef(1.0f, 1.0f + __expf(-x));
}
__device__ __forceinline__ float tanhfast(float x) {
    return 2.0f * sigf(2.0f * x) - 1.0f;
}

// cell update on a packed pair of batch lanes; gate order i, j, f, o
__device__ __forceinline__ void cell2(ull zi, ull zj, ull zf, ull zo,
                                      ull& c, float& h0, float& h1)
{
    float i0,i1,j0,j1,f0,f1,o0,o1,c0,c1;
    unpack2(zi,i0,i1); unpack2(zj,j0,j1);
    unpack2(zf,f0,f1); unpack2(zo,o0,o1);
    unpack2(c,c0,c1);
    c0 = sigf(f0 + 1.0f) * c0 + sigf(i0) * tanhfast(j0);
    c1 = sigf(f1 + 1.0f) * c1 + sigf(i1) * tanhfast(j1);
    h0 = sigf(o0) * tanhfast(c0);
    h1 = sigf(o1) * tanhfast(c1);
    c = pack2(c0, c1);
}

// 4-gate x 2-packed-batch tile (4 batch lanes per thread).
template<int KN, int WS>
__device__ __forceinline__ void gemm2(ull (&acc)[4][2],
                                      const ull* __restrict__ wd,
                                      const float* __restrict__ a)
{
    #pragma unroll 5
    for (int k = 0; k < KN; ++k) {
        ulonglong2 w01 = *(const ulonglong2*)(wd);
        ulonglong2 w23 = *(const ulonglong2*)(wd + 2);
        ulonglong2 av  = *(const ulonglong2*)(a);
        wd += WS; a += BTP;
        acc[0][0] = fma2(w01.x, av.x, acc[0][0]);
        acc[0][1] = fma2(w01.x, av.y, acc[0][1]);
        acc[1][0] = fma2(w01.y, av.x, acc[1][0]);
        acc[1][1] = fma2(w01.y, av.y, acc[1][1]);
        acc[2][0] = fma2(w23.x, av.x, acc[2][0]);
        acc[2][1] = fma2(w23.x, av.y, acc[2][1]);
        acc[3][0] = fma2(w23.y, av.x, acc[3][0]);
        acc[3][1] = fma2(w23.y, av.y, acc[3][1]);
    }
}

// ====================== x transpose: [B][T][D] -> [T][D][B] ======================
#define TT 256
__global__ void __launch_bounds__(TT)
xpose_kernel(const float* __restrict__ x)
{
    __shared__ float s[DIN * 65];
    const int t  = blockIdx.x;          // 0..299
    const int b0 = blockIdx.y * 64;     // batch tile
    const int tid = threadIdx.x;

    // load 64 rows of 39 floats (coalesced within each row)
    for (int i = tid; i < 64 * DIN; i += TT) {
        int b = i / DIN, d = i - b * DIN;
        s[d * 65 + b] = x[((size_t)(b0 + b) * T_STEPS + t) * DIN + d];
    }
    __syncthreads();
    // store coalesced 64-float rows per (t, d)
    for (int i = tid; i < DIN * 64; i += TT) {
        int d = i >> 6, b = i & 63;
        g_xT[((size_t)t * DIN + d) * BATCH + b0 + b] = s[d * 65 + b];
    }
}

extern __shared__ float smem[];

__global__ void __launch_bounds__(NT)
lstm_kernel(const float* __restrict__ fw_W1, const float* __restrict__ fw_b1,
            const float* __restrict__ fw_W2, const float* __restrict__ fw_b2,
            const float* __restrict__ bw_W1, const float* __restrict__ bw_b1,
            const float* __restrict__ bw_W2, const float* __restrict__ bw_b2)
{
    const int dir = blockIdx.y;
    const int b0  = blockIdx.x * BT;
    const int tid = threadIdx.x;

    float* W1d = smem + OFF_W1D;
    float* W2d = smem + OFF_W2D;
    float* b1p = smem + OFF_B1;
    float* b2p = smem + OFF_B2;
    float* xT  = smem + OFF_X;
    float* h1T = smem + OFF_H1;
    float* h2T = smem + OFF_H2;

    const float* W1g = dir ? bw_W1 : fw_W1;
    const float* b1g = dir ? bw_b1 : fw_b1;
    const float* W2g = dir ? bw_W2 : fw_W2;
    const float* b2g = dir ? bw_b2 : fw_b2;

    // permute (unit-major gate order i,j,f,o) + duplicate weights for f32x2.
    for (int i = tid; i < K1*G1P; i += NT) {
        int k = i / G1P, col = i - k * G1P;
        int u = col >> 2, g = col & 3;
        float w = (u < H1D) ? W1g[k*G1 + g*H1D + u] : 0.f;
        W1d[k*2*G1P + 2*col]     = w;
        W1d[k*2*G1P + 2*col + 1] = w;
    }
    for (int i = tid; i < K2*G2; i += NT) {
        int k = i / G2, col = i - k * G2;
        int u = col >> 2, g = col & 3;
        float w = W2g[k*G2 + g*H2D + u];
        W2d[k*2*G2 + 2*col]     = w;
        W2d[k*2*G2 + 2*col + 1] = w;
    }
    for (int i = tid; i < G1P; i += NT) {
        int u = i >> 2, g = i & 3;
        b1p[i] = (u < H1D) ? b1g[g*H1D + u] : 0.f;
    }
    for (int i = tid; i < G2; i += NT) { int u = i >> 2, g = i & 3; b2p[i] = b2g[g*H2D + u]; }
    for (int i = tid; i < H1_BUF; i += NT) { h1T[i] = 0.f; h1T[H1_BUF + i] = 0.f; }
    for (int i = tid; i < H2_BUF; i += NT) { h2T[i] = 0.f; h2T[H2_BUF + i] = 0.f; }

    // stage x for t=0 into buffer 0 (coalesced from g_xT)
    {
        const int tx0 = dir ? (T_STEPS - 1) : 0;
        for (int i = tid; i < DIN*16; i += NT) {
            int d = i >> 4, r = i & 15;
            *(float4*)(xT + d*BTP + r*4) =
                *(const float4*)(&g_xT[((size_t)tx0*DIN + d)*BATCH + b0 + r*4]);
        }
    }
    __syncthreads();

    const int unit = tid >> 4;          // 0..35 (35 = dummy)
    const int bcol = (tid & 15) * 4;    // 4 batch lanes per thread

    ull c1r[2] = {0,0};
    ull c2r[2] = {0,0};

    int cur = 0;

    for (int t = 0; t < T_STEPS; ++t) {
        const int nxt = cur ^ 1;
        const float* xc  = xT  + cur * X_BUF;
        const float* h1c = h1T + cur * H1_BUF;
        float*       h1n = h1T + nxt * H1_BUF;
        const float* h2c = h2T + cur * H2_BUF;
        float*       h2n = h2T + nxt * H2_BUF;

        // ====== Phase A: layer 1 — all 576 threads, one task each ======
        {
            ull acc[4][2];
            #pragma unroll
            for (int g = 0; g < 4; ++g) {
                float bb = b1p[unit*4 + g];
                ull bp = pack2(bb, bb);
                acc[g][0] = bp; acc[g][1] = bp;
            }
            const ull* wd = (const ull*)W1d + unit*4;
            gemm2<DIN, G1P>(acc, wd,             xc  + bcol);
            gemm2<H1D, G1P>(acc, wd + DIN*G1P,   h1c + bcol);

            float h[4];
            cell2(acc[0][0], acc[1][0], acc[2][0], acc[3][0], c1r[0], h[0], h[1]);
            cell2(acc[0][1], acc[1][1], acc[2][1], acc[3][1], c1r[1], h[2], h[3]);
            *(float4*)(h1n + unit*BTP + bcol) = make_float4(h[0], h[1], h[2], h[3]);
        }
        __syncthreads();

        // ====== Phase B: layer 2 (threads 0..479) + x staging (480..575) ======
        if (tid < 480) {
            ull acc[4][2];
            #pragma unroll
            for (int g = 0; g < 4; ++g) {
                float bb = b2p[unit*4 + g];
                ull bp = pack2(bb, bb);
                acc[g][0] = bp; acc[g][1] = bp;
            }
            const ull* wd = (const ull*)W2d + unit*4;
            gemm2<H1D, G2>(acc, wd,            h1n + bcol);
            gemm2<H2D, G2>(acc, wd + H1D*G2,   h2c + bcol);

            float h[4];
            cell2(acc[0][0], acc[1][0], acc[2][0], acc[3][0], c2r[0], h[0], h[1]);
            cell2(acc[0][1], acc[1][1], acc[2][1], acc[3][1], c2r[1], h[2], h[3]);
            *(float4*)(h2n + unit*BTP + bcol) = make_float4(h[0], h[1], h[2], h[3]);

            const int tx = dir ? (T_STEPS - 1 - t) : t;
            // coalesced: [t][feat][batch]
            *(float4*)(&g_hbuf[((size_t)(tx*60 + dir*H2D + unit))*BATCH + b0 + bcol]) =
                make_float4(h[0], h[1], h[2], h[3]);
        } else if (t + 1 < T_STEPS) {
            // warps 15..17 stage x_{t+1} (coalesced float4 from g_xT)
            const int txn = dir ? (T_STEPS - 2 - t) : (t + 1);
            float* xn = xT + nxt * X_BUF;
            #pragma unroll 4
            for (int i = tid - 480; i < DIN*16; i += 96) {
                int d = i >> 4, r = i & 15;
                *(float4*)(xn + d*BTP + r*4) =
                    *(const float4*)(&g_xT[((size_t)txn*DIN + d)*BATCH + b0 + r*4]);
            }
        }
        __syncthreads();
        cur = nxt;
    }
}

// =============================== FC head ===================================
#define FCT 128
#define FOFF_W1 0                       // 60*52 (padded cols 50,51 = 0)
#define FOFF_W2 (FOFF_W1 + 60*52)       // size 2000
#define FOFF_W3 (FOFF_W2 + 50*40)       // size 80
#define FOFF_B1 (FOFF_W3 + 80)          // size 52
#define FOFF_B2 (FOFF_B1 + 52)          // size 40
#define FOFF_B3 (FOFF_B2 + 40)          // size 4
#define FSM_FLOATS (FOFF_B3 + 4)        // 5296 floats = 21184 B (no INs stage)

__global__ void __launch_bounds__(FCT)
fc_kernel(const float* __restrict__ Wf1, const float* __restrict__ bf1,
          const float* __restrict__ Wf2, const float* __restrict__ bf2,
          const float* __restrict__ Wf3, const float* __restrict__ bf3,
          float* __restrict__ out)
{
    extern __shared__ float fsm[];
    float* W1s = fsm + FOFF_W1;
    float* W2s = fsm + FOFF_W2;
    float* W3s = fsm + FOFF_W3;
    float* B1s = fsm + FOFF_B1;
    float* B2s = fsm + FOFF_B2;
    float* B3s = fsm + FOFF_B3;

    const int tid = threadIdx.x;

    for (int i = tid; i < 60*52; i += FCT) {
        int k = i / 52, j = i - k * 52;
        W1s[i] = (j < 50) ? Wf1[k*50 + j] : 0.f;
    }
    for (int i = tid; i < 50*40; i += FCT) W2s[i] = Wf2[i];
    for (int i = tid; i < 80;    i += FCT) W3s[i] = Wf3[i];
    for (int i = tid; i < 52;    i += FCT) B1s[i] = (i < 50) ? bf1[i] : 0.f;
    for (int i = tid; i < 40;    i += FCT) B2s[i] = bf2[i];
    for (int i = tid; i < 2;     i += FCT) B3s[i] = bf3[i];
    __syncthreads();

    // block = (batch tile, timestep); hbuf [t][feat][B] reads coalesced per k
    const int bi = blockIdx.x & 31;          // 32 tiles of 128 batch
    const int t  = blockIdx.x >> 5;          // 0..299
    const int b0 = bi * FCT;
    const float* __restrict__ hb = &g_hbuf[(size_t)t * 60 * BATCH + b0 + tid];

    // fc1: 60 -> 50 (padded 52), packed f32x2 accumulators, direct gmem reads
    ull acc1[26];
    #pragma unroll
    for (int j = 0; j < 26; ++j) acc1[j] = pack2(B1s[2*j], B1s[2*j+1]);
    #pragma unroll 4
    for (int k = 0; k < 60; ++k) {
        float v = hb[(size_t)k * BATCH];
        ull vv = pack2(v, v);
        #pragma unroll
        for (int j = 0; j < 13; ++j) {
            ulonglong2 w = *(const ulonglong2*)(W1s + k*52 + j*4);
            acc1[2*j]   = fma2(vv, w.x, acc1[2*j]);
            acc1[2*j+1] = fma2(vv, w.y, acc1[2*j+1]);
        }
    }
    float a1[52];
    #pragma unroll
    for (int j = 0; j < 26; ++j) {
        float lo, hi; unpack2(acc1[j], lo, hi);
        a1[2*j]   = fmaxf(lo, 0.f);
        a1[2*j+1] = fmaxf(hi, 0.f);
    }

    // fc2: 50 -> 40
    ull acc2[20];
    #pragma unroll
    for (int j = 0; j < 20; ++j) acc2[j] = pack2(B2s[2*j], B2s[2*j+1]);
    #pragma unroll 5
    for (int k = 0; k < 50; ++k) {
        ull vv = pack2(a1[k], a1[k]);
        #pragma unroll
        for (int j = 0; j < 10; ++j) {
            ulonglong2 w = *(const ulonglong2*)(W2s + k*40 + j*4);
            acc2[2*j]   = fma2(vv, w.x, acc2[2*j]);
            acc2[2*j+1] = fma2(vv, w.y, acc2[2*j+1]);
        }
    }
    float a2[40];
    #pragma unroll
    for (int j = 0; j < 20; ++j) {
        float lo, hi; unpack2(acc2[j], lo, hi);
        a2[2*j]   = fmaxf(lo, 0.f);
        a2[2*j+1] = fmaxf(hi, 0.f);
    }

    // out: 40 -> 2
    float o0 = B3s[0], o1 = B3s[1];
    #pragma unroll
    for (int k = 0; k < 40; ++k) {
        o0 = fmaf(a2[k], W3s[2*k + 0], o0);
        o1 = fmaf(a2[k], W3s[2*k + 1], o1);
    }
    // out layout [B][T][2]
    float2 ov = make_float2(o0, o1);
    *(float2*)(&out[((size_t)(b0 + tid) * T_STEPS + t) * 2]) = ov;
}

// ============================================================================
extern "C" void kernel_launch(void* const* d_in, const int* in_sizes, int n_in,
                              void* d_out, int out_size)
{
    const float* x     = (const float*)d_in[0];
    const float* fw_W1 = (const float*)d_in[1];
    const float* fw_b1 = (const float*)d_in[2];
    const float* fw_W2 = (const float*)d_in[3];
    const float* fw_b2 = (const float*)d_in[4];
    const float* bw_W1 = (const float*)d_in[5];
    const float* bw_b1 = (const float*)d_in[6];
    const float* bw_W2 = (const float*)d_in[7];
    const float* bw_b2 = (const float*)d_in[8];
    const float* Wf1   = (const float*)d_in[9];
    const float* bf1   = (const float*)d_in[10];
    const float* Wf2   = (const float*)d_in[11];
    const float* bf2   = (const float*)d_in[12];
    const float* Wf3   = (const float*)d_in[13];
    const float* bf3   = (const float*)d_in[14];

    cudaFuncSetAttribute(lstm_kernel, cudaFuncAttributeMaxDynamicSharedMemorySize,
                         SM_FLOATS * (int)sizeof(float));
    cudaFuncSetAttribute(fc_kernel, cudaFuncAttributeMaxDynamicSharedMemorySize,
                         FSM_FLOATS * (int)sizeof(float));

    xpose_kernel<<<dim3(T_STEPS, BATCH/64), TT>>>(x);

    lstm_kernel<<<dim3(NBLK, 2), NT, SM_FLOATS * sizeof(float)>>>(
        fw_W1, fw_b1, fw_W2, fw_b2, bw_W1, bw_b1, bw_W2, bw_b2);

    fc_kernel<<<32 * T_STEPS, FCT, FSM_FLOATS * sizeof(float)>>>(
        Wf1, bf1, Wf2, bf2, Wf3, bf3, (float*)d_out);
}